// round 1
// baseline (speedup 1.0000x reference)
#include <cuda_runtime.h>
#include <cuda_bf16.h>

// Renderer: B=2 batches, N=2048 points, S=128 image, K=16 points per pixel.
// Strategy: each block handles 256 pixels of one batch. It first projects all
// 2048 points of that batch into shared memory (float4: x_ndc, y_ndc, z, pad),
// using a 1e30 sentinel for invisible points (z <= ZNEAR) so they can never
// pass the d2 < R^2 test. Then each thread brute-forces all 2048 points for
// its pixel, maintaining a K=16 insertion-sorted (by z ascending, stable in
// index) hit list, and finally alpha-composites front-to-back.

#define S_IMG   128
#define NPTS    2048
#define KHITS   16
#define RADIUS  0.02f
#define RAD2    (RADIUS * RADIUS)
#define INV_RAD2 (1.0f / RAD2)
#define ZNEAR   1.0f
// focal = 1 / tan(60deg / 2) = sqrt(3)
#define FOCAL   1.7320508075688772f

__global__ __launch_bounds__(256) void render_kernel(
    const float* __restrict__ points,   // [B, N, 3]
    const float* __restrict__ eye,      // [B, 3]
    const float* __restrict__ colors,   // [B, N, 3]
    float* __restrict__ out)            // [B, S, S, 3]
{
    __shared__ float4 sp[NPTS];

    const int b   = blockIdx.y;
    const int tid = threadIdx.x;

    // ---- Camera basis (computed redundantly per thread; trivial cost) ----
    const float ex = eye[b * 3 + 0];
    const float ey = eye[b * 3 + 1];
    const float ez = eye[b * 3 + 2];

    // z axis = normalize(-eye)
    float zn = rsqrtf(ex * ex + ey * ey + ez * ez);
    float zax = -ex * zn, zay = -ey * zn, zaz = -ez * zn;
    // x axis = normalize(up x z), up = (0,1,0) -> (z.z, 0, -z.x)
    float xax = zaz, xaz = -zax;
    float xn = rsqrtf(xax * xax + xaz * xaz);
    xax *= xn; xaz *= xn;
    // y axis = z x x  (with x.y == 0)
    float yax = zay * xaz;
    float yay = zaz * xax - zax * xaz;
    float yaz = -zay * xax;

    // ---- Project all points of this batch into shared memory ----
    for (int i = tid; i < NPTS; i += blockDim.x) {
        const float* p = points + (size_t)(b * NPTS + i) * 3;
        float dx = p[0] - ex;
        float dy = p[1] - ey;
        float dz = p[2] - ez;
        float cz = dx * zax + dy * zay + dz * zaz;
        if (cz > ZNEAR) {
            float cx = dx * xax + dz * xaz;          // x.y == 0
            float cy = dx * yax + dy * yay + dz * yaz;
            float s  = FOCAL / cz;
            sp[i] = make_float4(cx * s, cy * s, cz, 0.0f);
        } else {
            sp[i] = make_float4(1e30f, 1e30f, 1e30f, 0.0f);
        }
    }
    __syncthreads();

    // ---- Pixel assignment ----
    const int p    = blockIdx.x * blockDim.x + tid;   // 0 .. S*S-1
    const int row  = p >> 7;
    const int col  = p & (S_IMG - 1);
    const float pxc = 1.0f - (2.0f * (float)col + 1.0f) / (float)S_IMG;
    const float pyc = 1.0f - (2.0f * (float)row + 1.0f) / (float)S_IMG;

    // ---- K-nearest-in-depth hit list (insertion sort; hits are rare) ----
    float zb[KHITS];
    float db[KHITS];
    int   ib[KHITS];
    int   cnt = 0;

    #pragma unroll 4
    for (int i = 0; i < NPTS; i++) {
        float4 q = sp[i];
        float ddx = pxc - q.x;
        float ddy = pyc - q.y;
        float d2  = ddx * ddx + ddy * ddy;
        if (d2 < RAD2) {
            float z = q.z;
            if (cnt < KHITS) {
                int j = cnt++;
                while (j > 0 && zb[j - 1] > z) {
                    zb[j] = zb[j - 1]; db[j] = db[j - 1]; ib[j] = ib[j - 1];
                    j--;
                }
                zb[j] = z; db[j] = d2; ib[j] = i;
            } else if (z < zb[KHITS - 1]) {
                int j = KHITS - 1;
                while (j > 0 && zb[j - 1] > z) {
                    zb[j] = zb[j - 1]; db[j] = db[j - 1]; ib[j] = ib[j - 1];
                    j--;
                }
                zb[j] = z; db[j] = d2; ib[j] = i;
            }
        }
    }

    // ---- Front-to-back alpha compositing ----
    float T = 1.0f, r = 0.0f, g = 0.0f, bl = 0.0f;
    for (int k = 0; k < cnt; k++) {
        float a = 1.0f - db[k] * INV_RAD2;
        a = fminf(fmaxf(a, 0.0f), 1.0f);
        const float* c = colors + (size_t)(b * NPTS + ib[k]) * 3;
        float w = a * T;
        r  += w * c[0];
        g  += w * c[1];
        bl += w * c[2];
        T *= (1.0f - a);
    }

    float* o = out + (size_t)((b * S_IMG + row) * S_IMG + col) * 3;
    o[0] = r; o[1] = g; o[2] = bl;
}

extern "C" void kernel_launch(void* const* d_in, const int* in_sizes, int n_in,
                              void* d_out, int out_size) {
    const float* points = (const float*)d_in[0];
    const float* eye    = (const float*)d_in[1];
    const float* colors = (const float*)d_in[2];
    float* out          = (float*)d_out;

    const int B = in_sizes[1] / 3;                 // eye is [B,3]
    dim3 grid(S_IMG * S_IMG / 256, B);
    render_kernel<<<grid, 256>>>(points, eye, colors, out);
}

// round 2
// speedup vs baseline: 3.6850x; 3.6850x over previous
#include <cuda_runtime.h>
#include <cuda_bf16.h>

// Renderer: B=2, N=2048 points, S=128 image, K=16 per pixel, alpha composite.
//
// Two-kernel tiled approach:
//   K1: project all points to NDC once -> g_proj[b][i] = (x, y, z) with a
//       1e30 sentinel for points with z <= ZNEAR.
//   K2: one 64-thread block per 8x8-pixel tile. Block compacts the points
//       whose NDC pos lies in the tile bbox (expanded by RADIUS) into shared
//       memory, then each thread (one pixel) z-buffers only those candidates.
// Insertion sort keys on (z, index) so the result is deterministic regardless
// of the atomic compaction order, and matches top_k's index-stable ties.

#define S_IMG    128
#define NPTS     2048
#define KHITS    16
#define RADIUS   0.02f
#define RAD2     (RADIUS * RADIUS)
#define INV_RAD2 (1.0f / RAD2)
#define ZNEAR    1.0f
#define FOCAL    1.7320508075688772f   // 1 / tan(30 deg)
#define TILE     8
#define CAP      512                   // per-tile candidate capacity

__device__ float4 g_proj[8 * NPTS];    // up to 8 batches of scratch

// ---------------------------------------------------------------- kernel 1 --
__global__ __launch_bounds__(256) void project_kernel(
    const float* __restrict__ points,   // [B, N, 3]
    const float* __restrict__ eye)      // [B, 3]
{
    const int g = blockIdx.x * blockDim.x + threadIdx.x;
    const int b = g / NPTS;
    const int i = g - b * NPTS;

    const float ex = eye[b * 3 + 0];
    const float ey = eye[b * 3 + 1];
    const float ez = eye[b * 3 + 2];

    // camera basis (look-at origin, up = +y)
    float zn  = rsqrtf(ex * ex + ey * ey + ez * ez);
    float zax = -ex * zn, zay = -ey * zn, zaz = -ez * zn;
    float xax = zaz, xaz = -zax;                 // up x z (x.y == 0)
    float xn  = rsqrtf(xax * xax + xaz * xaz);
    xax *= xn; xaz *= xn;
    float yax = zay * xaz;
    float yay = zaz * xax - zax * xaz;
    float yaz = -zay * xax;

    const float* p = points + (size_t)g * 3;
    float dx = p[0] - ex, dy = p[1] - ey, dz = p[2] - ez;
    float cz = dx * zax + dy * zay + dz * zaz;

    float4 o;
    if (cz > ZNEAR) {
        float cx = dx * xax + dz * xaz;
        float cy = dx * yax + dy * yay + dz * yaz;
        float s  = FOCAL / cz;
        o = make_float4(cx * s, cy * s, cz, 0.0f);
    } else {
        o = make_float4(1e30f, 1e30f, 1e30f, 0.0f);
    }
    g_proj[g] = o;
}

// ---------------------------------------------------------------- kernel 2 --
__global__ __launch_bounds__(64) void render_tiled_kernel(
    const float* __restrict__ colors,   // [B, N, 3]
    float* __restrict__ out)            // [B, S, S, 3]
{
    __shared__ float4 sl[CAP];
    __shared__ int s_cnt;

    const int b   = blockIdx.z;
    const int tcx = blockIdx.x;          // tile col index
    const int tcy = blockIdx.y;          // tile row index
    const int tid = threadIdx.x;         // 0..63

    if (tid == 0) s_cnt = 0;
    __syncthreads();

    // tile NDC bounds (px decreases with col, py decreases with row)
    const int c0 = tcx * TILE, r0 = tcy * TILE;
    const float inv = 1.0f / (float)S_IMG;
    const float xhi = 1.0f - (2.0f * c0 + 1.0f) * inv + RADIUS;
    const float xlo = 1.0f - (2.0f * (c0 + TILE - 1) + 1.0f) * inv - RADIUS;
    const float yhi = 1.0f - (2.0f * r0 + 1.0f) * inv + RADIUS;
    const float ylo = 1.0f - (2.0f * (r0 + TILE - 1) + 1.0f) * inv - RADIUS;

    // compact candidates for this tile
    const float4* proj = g_proj + b * NPTS;
    for (int i = tid; i < NPTS; i += 64) {
        float4 q = proj[i];
        if (q.x >= xlo && q.x <= xhi && q.y >= ylo && q.y <= yhi) {
            int p = atomicAdd(&s_cnt, 1);
            if (p < CAP) sl[p] = make_float4(q.x, q.y, q.z, __int_as_float(i));
        }
    }
    __syncthreads();
    const int cnt = min(s_cnt, CAP);

    // this thread's pixel
    const int col = c0 + (tid & (TILE - 1));
    const int row = r0 + (tid >> 3);
    const float pxc = 1.0f - (2.0f * col + 1.0f) * inv;
    const float pyc = 1.0f - (2.0f * row + 1.0f) * inv;

    // K nearest-in-depth hits, keyed (z, index) for determinism + top_k ties
    float zb[KHITS];
    float db[KHITS];
    int   ib[KHITS];
    int   nh = 0;

    for (int j = 0; j < cnt; j++) {
        float4 q = sl[j];
        float ddx = pxc - q.x;
        float ddy = pyc - q.y;
        float d2  = ddx * ddx + ddy * ddy;
        if (d2 < RAD2) {
            float z = q.z;
            int   i = __float_as_int(q.w);
            if (nh < KHITS) {
                int k = nh++;
                while (k > 0 && (zb[k-1] > z || (zb[k-1] == z && ib[k-1] > i))) {
                    zb[k] = zb[k-1]; db[k] = db[k-1]; ib[k] = ib[k-1]; k--;
                }
                zb[k] = z; db[k] = d2; ib[k] = i;
            } else if (z < zb[KHITS-1] ||
                       (z == zb[KHITS-1] && i < ib[KHITS-1])) {
                int k = KHITS - 1;
                while (k > 0 && (zb[k-1] > z || (zb[k-1] == z && ib[k-1] > i))) {
                    zb[k] = zb[k-1]; db[k] = db[k-1]; ib[k] = ib[k-1]; k--;
                }
                zb[k] = z; db[k] = d2; ib[k] = i;
            }
        }
    }

    // front-to-back alpha compositing
    float T = 1.0f, r = 0.0f, g = 0.0f, bl = 0.0f;
    for (int k = 0; k < nh; k++) {
        float a = 1.0f - db[k] * INV_RAD2;
        a = fminf(fmaxf(a, 0.0f), 1.0f);
        const float* c = colors + (size_t)(b * NPTS + ib[k]) * 3;
        float w = a * T;
        r  += w * c[0];
        g  += w * c[1];
        bl += w * c[2];
        T *= (1.0f - a);
    }

    float* o = out + (size_t)((b * S_IMG + row) * S_IMG + col) * 3;
    o[0] = r; o[1] = g; o[2] = bl;
}

// ----------------------------------------------------------------- launch ---
extern "C" void kernel_launch(void* const* d_in, const int* in_sizes, int n_in,
                              void* d_out, int out_size) {
    const float* points = (const float*)d_in[0];
    const float* eye    = (const float*)d_in[1];
    const float* colors = (const float*)d_in[2];
    float* out          = (float*)d_out;

    const int B = in_sizes[1] / 3;     // eye is [B,3]

    project_kernel<<<(B * NPTS) / 256, 256>>>(points, eye);

    dim3 grid(S_IMG / TILE, S_IMG / TILE, B);
    render_tiled_kernel<<<grid, 64>>>(colors, out);
}